// round 12
// baseline (speedup 1.0000x reference)
#include <cuda_runtime.h>
#include <cuda_bf16.h>
#include <cstdint>
#include <math.h>

// ---------------------------------------------------------------------------
// RoiProposal: 2 kernels.
//  1) cooperative front (4 blocks/SM co-resident, 5 grid barriers):
//     zero -> proposal(+hist) -> thresh(blk0) -> compact -> rankscatter -> mask
//  2) single-block greedy NMS scan + select + output
// ---------------------------------------------------------------------------

#define NPROP 36864
#define KTOP  6000
#define KPAD  6016
#define WORDS 188
#define TILES 188
#define NOUT  300
#define NBIN  16384      // histogram bins (key >> 18)

// ------------------------------ scratch --------------------------------------
__device__ unsigned g_skey[NPROP];
__device__ __align__(16) int g_hist[NBIN];
__device__ int g_bcur[NBIN];
__device__ __align__(16) int g_sufx[NBIN];
__device__ int g_tb, g_S;
__device__ unsigned long long g_k64[NPROP];   // survivors, bin-grouped
__device__ int g_iS[NPROP];
__device__ float4 g_pbox[NPROP];
__device__ float4 g_tbox[KPAD];
__device__ float  g_ta[KPAD];
__device__ unsigned g_maskT[(size_t)WORDS * KPAD];   // [word][row]
__device__ unsigned g_bcount;    // barrier arrivals (self-resetting)
__device__ unsigned g_bsense;    // barrier sense

__constant__ float c_AW[9] = {184.f, 368.f, 736.f, 128.f, 256.f, 512.f, 88.f, 176.f, 352.f};
__constant__ float c_AH[9] = {96.f, 192.f, 384.f, 128.f, 256.f, 512.f, 176.f, 352.f, 704.f};

// ------------------------------ grid barrier (co-resident grid) --------------
__device__ __forceinline__ void gsync(unsigned& sense) {
    __syncthreads();
    if (threadIdx.x == 0) {
        sense ^= 1u;
        __threadfence();
        unsigned old = atomicAdd(&g_bcount, 1u);
        if (old == gridDim.x - 1) {
            g_bcount = 0;
            __threadfence();
            atomicExch(&g_bsense, sense);
        } else {
            while (atomicAdd(&g_bsense, 0u) != sense) { }
            __threadfence();
        }
    }
    __syncthreads();
}

// ------------------------------ 256-thread inclusive scan --------------------
__device__ __forceinline__ int bscan256(int v, int t, int* ws) {
    #pragma unroll
    for (int d = 1; d < 32; d <<= 1) {
        int n = __shfl_up_sync(0xFFFFFFFFu, v, d);
        if ((t & 31) >= d) v += n;
    }
    if ((t & 31) == 31) ws[t >> 5] = v;
    __syncthreads();
    if (t < 32) {
        int w = (t < 8) ? ws[t] : 0;
        #pragma unroll
        for (int d = 1; d < 8; d <<= 1) {
            int n = __shfl_up_sync(0xFFFFFFFFu, w, d);
            if (t >= d) w += n;
        }
        if (t < 8) ws[t] = w;
    }
    __syncthreads();
    if (t >= 32) v += ws[(t >> 5) - 1];
    __syncthreads();
    return v;
}

// =============================================================================
// Kernel 1: cooperative front. 256 thr, 4 blocks/SM co-resident.
// =============================================================================
__global__ void __launch_bounds__(256, 4) front_kernel(
    const float* __restrict__ cls, const float* __restrict__ bbox)
{
    const int t = threadIdx.x;
    const int blk = blockIdx.x;
    const int G = gridDim.x;
    const int gtid = blk * 256 + t;
    const int gstr = G * 256;
    unsigned sense = *((volatile unsigned*)&g_bsense);

    __shared__ int s_ws[8];
    __shared__ float4 sb[32];
    __shared__ float sa[32];

    // ---- P0: zero scratch + pads ----
    for (int i = gtid; i < NBIN; i += gstr) { g_hist[i] = 0; g_bcur[i] = 0; }
    for (int i = KTOP + gtid; i < KPAD; i += gstr) {
        g_tbox[i] = make_float4(-1e8f, -1e8f, -1e8f, -1e8f);
        g_ta[i] = 1.f;
    }
    gsync(sense);

    // ---- P1: proposals + keys + histogram ----
    if (gtid < NPROP) {
        int i = gtid;
        int a = i % 9;
        int cell = i / 9;
        float axc = (float)((cell % 64) * 16 + 8);
        float ayc = (float)((cell / 64) * 16 + 8);
        float aw = c_AW[a];
        float ah = c_AH[a];

        const float* cp = cls + cell * 18 + a * 2;
        float s0 = cp[0], s1 = cp[1];
        const float* dp = bbox + cell * 36 + a * 4;
        float dx = dp[0], dy = dp[1], dw = dp[2], dh = dp[3];

        // explicit .rn ops (no FMA contraction; match XLA codegen)
        float pxc = __fadd_rn(__fmul_rn(dx, aw), axc);
        float pyc = __fadd_rn(__fmul_rn(dy, ah), ayc);
        float pw  = __fmul_rn(expf(dw), aw);
        float ph  = __fmul_rn(expf(dh), ah);
        float hx  = __fmul_rn(0.5f, pw);
        float hy  = __fmul_rn(0.5f, ph);
        float x1 = fminf(fmaxf(__fsub_rn(pxc, hx), 0.f), 1023.f);
        float x2 = fminf(fmaxf(__fadd_rn(pxc, hx), 0.f), 1023.f);
        float y1 = fminf(fmaxf(__fsub_rn(pyc, hy), 0.f), 1023.f);
        float y2 = fminf(fmaxf(__fadd_rn(pyc, hy), 0.f), 1023.f);

        bool valid = (__fadd_rn(__fsub_rn(x2, x1), 1.f) >= 16.f) &&
                     (__fadd_rn(__fsub_rn(y2, y1), 1.f) >= 16.f);

        float m  = fmaxf(s0, s1);
        float e0 = expf(__fsub_rn(s0, m));
        float e1 = expf(__fsub_rn(s1, m));
        float sc = __fdiv_rn(e1, __fadd_rn(e0, e1));
        if (!valid) sc = -INFINITY;

        g_pbox[i] = make_float4(x1, y1, x2, y2);

        unsigned ub = __float_as_uint(sc);
        ub = (ub & 0x80000000u) ? ~ub : (ub | 0x80000000u);
        g_skey[i] = ub;
        atomicAdd(&g_hist[ub >> 18], 1);
    }
    gsync(sense);

    // ---- P2: threshold + suffix offsets (block 0 only; two-pass, low regs) ----
    if (blk == 0) {
        // chunk t covers bins [lo, lo+63], chunks ordered DESCENDING by bin
        int lo = NBIN - 64 * (t + 1);
        int base4 = lo >> 2;
        int sum = 0;
        #pragma unroll
        for (int k = 0; k < 16; k++) {
            int4 v = reinterpret_cast<const int4*>(g_hist)[base4 + k];
            sum += v.x + v.y + v.z + v.w;
        }
        int incl = bscan256(sum, t, s_ws);
        int run = incl - sum;        // anchors in bins strictly above this chunk
        for (int kk = 63; kk >= 0; kk--) {   // descending bins within chunk
            int bin = lo + kk;
            int h = g_hist[bin];
            g_sufx[bin] = run;
            int nrun = run + h;
            if (run < KTOP && nrun >= KTOP) { g_tb = bin; g_S = nrun; }
            run = nrun;
        }
    }
    gsync(sense);

    // ---- P3: compaction into bin-grouped slots ----
    if (gtid < NPROP) {
        unsigned key = g_skey[gtid];
        int bin = (int)(key >> 18);
        if (bin >= g_tb) {
            int pos = g_sufx[bin] + atomicAdd(&g_bcur[bin], 1);
            g_k64[pos] = ((unsigned long long)key << 32) |
                         (unsigned long long)(0xFFFFFFFFu - (unsigned)gtid);
            g_iS[pos] = gtid;
        }
    }
    gsync(sense);

    // ---- P4: exact rank + scatter (unique u64 keys => exact jax tie order) ----
    if (gtid < g_S) {
        unsigned long long ki = g_k64[gtid];
        unsigned bin = (unsigned)(ki >> 50);
        int b0 = g_sufx[bin];
        int nb = g_hist[bin];
        int r = b0;
        for (int m = 0; m < nb; m++) r += (g_k64[b0 + m] > ki);
        if (r < KTOP) {
            float4 f = g_pbox[g_iS[gtid]];
            g_tbox[r] = f;
            g_ta[r] = __fmul_rn(__fadd_rn(__fsub_rn(f.z, f.x), 1.f),
                                __fadd_rn(__fsub_rn(f.w, f.y), 1.f));
        }
    }
    gsync(sense);

    // ---- P5: IoU suppression bitmask (256-row x 32-col tiles, grid-strided) ----
    for (int m = blk; m < 24 * 188; m += G) {
        int rb = m / 188;
        int wx = m - rb * 188;
        if (wx < 8 * rb) continue;           // tile fully below diagonal (uniform)
        __syncthreads();
        if (t < 32) {
            int c = wx * 32 + t;
            sb[t] = g_tbox[c];
            sa[t] = g_ta[c];
        }
        __syncthreads();
        int r = rb * 256 + t;

        int cbase = wx * 32;
        unsigned mgt;
        if (r < cbase) mgt = 0xFFFFFFFFu;
        else { int d = r - cbase; mgt = (d >= 31) ? 0u : ~((2u << d) - 1u); }
        unsigned mlt = (wx == WORDS - 1) ? 0xFFFFu : 0xFFFFFFFFu;
        unsigned cmask = mgt & mlt;

        unsigned w = 0;
        if (r < KTOP && cmask) {
            float4 rbx = g_tbox[r];
            float ar = g_ta[r];
            #pragma unroll
            for (int b = 0; b < 32; b++) {
                float4 cb = sb[b];
                float ca = sa[b];
                float ix1 = fmaxf(rbx.x, cb.x);
                float iy1 = fmaxf(rbx.y, cb.y);
                float ix2 = fminf(rbx.z, cb.z);
                float iy2 = fminf(rbx.w, cb.w);
                float iw = fmaxf(__fadd_rn(__fsub_rn(ix2, ix1), 1.f), 0.f);
                float ih = fmaxf(__fadd_rn(__fsub_rn(iy2, iy1), 1.f), 0.f);
                float inter = __fmul_rn(iw, ih);
                float uni = __fsub_rn(__fadd_rn(ar, ca), inter);
                float iou = __fdiv_rn(inter, uni);
                if (iou > 0.7f) w |= (1u << b);
            }
            w &= cmask;
        }
        if (r < KPAD) g_maskT[(size_t)wx * KPAD + r] = w;
    }
}

// =============================================================================
// Kernel 2: single-block greedy NMS scan + select + output.
// =============================================================================
__device__ __forceinline__ void load_tile(unsigned (&dst)[32], int t, int T) {
    const uint4* q = reinterpret_cast<const uint4*>(
        &g_maskT[(size_t)t * KPAD + (size_t)T * 32]);
    #pragma unroll
    for (int i = 0; i < 8; i++) {
        uint4 v = q[i];
        dst[4*i+0] = v.x; dst[4*i+1] = v.y; dst[4*i+2] = v.z; dst[4*i+3] = v.w;
    }
}

__device__ __forceinline__ unsigned or_sel(const unsigned (&w)[32], unsigned km) {
    unsigned a0 = 0, a1 = 0, a2 = 0, a3 = 0;
    #pragma unroll
    for (int b = 0; b < 32; b += 4) {
        if (km & (1u << b))       a0 |= w[b];
        if (km & (1u << (b + 1))) a1 |= w[b + 1];
        if (km & (1u << (b + 2))) a2 |= w[b + 2];
        if (km & (1u << (b + 3))) a3 |= w[b + 3];
    }
    return (a0 | a1) | (a2 | a3);
}

__device__ __forceinline__ void diag_resolve(const unsigned (&D)[32], unsigned removed,
                                             unsigned& kept_out) {
    unsigned internal = removed, kept = 0u;
    #pragma unroll
    for (int b = 0; b < 32; b++) {
        if (!((internal >> b) & 1u)) { kept |= (1u << b); internal |= D[b]; }
    }
    kept_out = kept;
}

__global__ void __launch_bounds__(256, 1) scan_out_kernel(float* __restrict__ out) {
    const int t = threadIdx.x;
    __shared__ int s_ws[8];
    __shared__ unsigned s_keep[2];
    __shared__ int s_tot[2];
    __shared__ int s_sidx[NOUT];
    __shared__ int s_C;

    bool act = (t < WORDS);
    unsigned D[32], Abuf[32], Bbuf[32];
    unsigned removed = 0;
    int stop = TILES - 1;

    if (act) load_tile(D, t, t);
    if (act && t >= 1) load_tile(Abuf, t, 0);

    #pragma unroll 1
    for (int T = 0; T < TILES; T += 2) {
        if (act && t >= T + 2 && T + 1 < TILES) load_tile(Bbuf, t, T + 1);
        if (t == T) {
            unsigned kept;
            diag_resolve(D, removed, kept);
            s_keep[0] = kept;
            unsigned cv = (T == TILES - 1) ? (kept & 0xFFFFu) : kept;
            s_tot[0] = ((T == 0) ? 0 : s_tot[1]) + __popc(cv);
        }
        __syncthreads();
        {
            unsigned km = s_keep[0];
            if (act && t >= T) {
                if (t == T) removed |= or_sel(D, km);
                else        removed |= or_sel(Abuf, km);
            }
            if (s_tot[0] >= NOUT) { stop = T; break; }
        }
        if (T + 1 < TILES) {
            if (act && t >= T + 3 && T + 2 < TILES) load_tile(Abuf, t, T + 2);
            if (t == T + 1) {
                unsigned kept;
                diag_resolve(D, removed, kept);
                s_keep[1] = kept;
                unsigned cv = (T + 1 == TILES - 1) ? (kept & 0xFFFFu) : kept;
                s_tot[1] = s_tot[0] + __popc(cv);
            }
            __syncthreads();
            unsigned km = s_keep[1];
            if (act && t >= T + 1) {
                if (t == T + 1) removed |= or_sel(D, km);
                else            removed |= or_sel(Bbuf, km);
            }
            if (s_tot[1] >= NOUT) { stop = T + 1; break; }
        }
    }
    __syncthreads();

    // ---- select first 300 + output ----
    int L = min(KTOP, 32 * (stop + 1));
    int nb = L - 32 * t;
    nb = nb < 0 ? 0 : (nb > 32 ? 32 : nb);
    unsigned vmask = (nb >= 32) ? 0xFFFFFFFFu : ((nb > 0) ? ((1u << nb) - 1u) : 0u);

    unsigned rem = act ? removed : 0u;
    unsigned kept = (~rem) & vmask;
    int cnt = __popc(kept);
    int incl = bscan256(cnt, t, s_ws);
    int excl = incl - cnt;
    if (t == 255) s_C = incl;
    __syncthreads();
    int C = s_C;

    if (excl < NOUT && kept) {
        int r = excl;
        #pragma unroll 4
        for (int b = 0; b < 32; b++) {
            if ((kept >> b) & 1u) {
                if (r < NOUT) s_sidx[r] = t * 32 + b;
                r++;
            }
        }
    }
    __syncthreads();

    if (C < NOUT) {   // fill with suppressed (index ascending)
        unsigned sup = rem & vmask;
        int cnt2 = __popc(sup);
        int incl2 = bscan256(cnt2, t, s_ws);
        int b0 = C + (incl2 - cnt2);
        if (b0 < NOUT && sup) {
            #pragma unroll 4
            for (int b = 0; b < 32; b++) {
                if ((sup >> b) & 1u) {
                    if (b0 < NOUT) s_sidx[b0] = t * 32 + b;
                    b0++;
                }
            }
        }
        __syncthreads();
    }

    for (int r = t; r < NOUT; r += 256) {
        int idx = s_sidx[r];
        float4 f = g_tbox[idx];
        out[5 * r + 0] = 0.f;
        out[5 * r + 1] = f.x;
        out[5 * r + 2] = f.y;
        out[5 * r + 3] = f.z;
        out[5 * r + 4] = f.w;
    }
}

// ------------------------------ launch ---------------------------------------
extern "C" void kernel_launch(void* const* d_in, const int* in_sizes, int n_in,
                              void* d_out, int out_size) {
    const float* cls  = (const float*)d_in[0];   // (1,64,64,18)
    const float* bbox = (const float*)d_in[1];   // (1,64,64,36)
    float* out = (float*)d_out;                  // (300,5)

    int dev = 0;
    cudaGetDevice(&dev);
    int sms = 0;
    cudaDeviceGetAttribute(&sms, cudaDevAttrMultiProcessorCount, dev);
    int maxb = 0;
    cudaOccupancyMaxActiveBlocksPerMultiprocessor(&maxb, front_kernel, 256, 0);
    if (maxb < 1) maxb = 1;
    if (maxb > 4) maxb = 4;
    int G = sms * maxb;          // all co-resident: grid barrier is safe

    front_kernel<<<G, 256>>>(cls, bbox);
    scan_out_kernel<<<1, 256>>>(out);
}

// round 13
// speedup vs baseline: 1.1832x; 1.1832x over previous
#include <cuda_runtime.h>
#include <cuda_bf16.h>
#include <cstdint>
#include <math.h>

// ---------------------------------------------------------------------------
// RoiProposal: 5 kernels.
//  proposal(+hist) -> thresh(+epoch) -> compact -> rankscatter ->
//  maskscan (block0 = greedy scan pipelined against mask producer blocks)
// ---------------------------------------------------------------------------

#define NPROP 36864
#define KTOP  6000
#define KPAD  6016
#define WORDS 188
#define TILES 188
#define NOUT  300
#define NBIN  16384      // histogram bins (key >> 18)
#define NRB   24         // 256-row chunks covering KPAD

// ------------------------------ scratch --------------------------------------
__device__ unsigned g_skey[NPROP];
__device__ __align__(16) int g_hist[NBIN];      // zeroed at end of maskscan
__device__ int g_bcur[NBIN];                    // zeroed at end of maskscan
__device__ __align__(16) int g_sufx[NBIN];
__device__ int g_tb, g_S;
__device__ unsigned long long g_k64[NPROP];     // survivors, bin-grouped
__device__ int g_iS[NPROP];
__device__ float4 g_pbox[NPROP];
__device__ float4 g_tbox[KPAD];
__device__ float  g_ta[KPAD];
__device__ unsigned g_maskT[(size_t)WORDS * KPAD];   // [word][row]
__device__ unsigned g_rowdone[NRB];             // monotonic (epoch-scaled)
__device__ unsigned g_epoch;                    // bumped once per launch chain

__constant__ float c_AW[9] = {184.f, 368.f, 736.f, 128.f, 256.f, 512.f, 88.f, 176.f, 352.f};
__constant__ float c_AH[9] = {96.f, 192.f, 384.f, 128.f, 256.f, 512.f, 176.f, 352.f, 704.f};

// ------------------------------ 256-thread inclusive scan --------------------
__device__ __forceinline__ int bscan256(int v, int t, int* ws) {
    #pragma unroll
    for (int d = 1; d < 32; d <<= 1) {
        int n = __shfl_up_sync(0xFFFFFFFFu, v, d);
        if ((t & 31) >= d) v += n;
    }
    if ((t & 31) == 31) ws[t >> 5] = v;
    __syncthreads();
    if (t < 32) {
        int w = (t < 8) ? ws[t] : 0;
        #pragma unroll
        for (int d = 1; d < 8; d <<= 1) {
            int n = __shfl_up_sync(0xFFFFFFFFu, w, d);
            if (t >= d) w += n;
        }
        if (t < 8) ws[t] = w;
    }
    __syncthreads();
    if (t >= 32) v += ws[(t >> 5) - 1];
    __syncthreads();
    return v;
}

// ------------------------------ 1) proposals + keys + histogram --------------
__global__ void proposal_kernel(const float* __restrict__ cls,
                                const float* __restrict__ bbox) {
    int i = blockIdx.x * blockDim.x + threadIdx.x;
    if (i >= NPROP) return;

    int a = i % 9;
    int cell = i / 9;
    float axc = (float)((cell % 64) * 16 + 8);
    float ayc = (float)((cell / 64) * 16 + 8);
    float aw = c_AW[a];
    float ah = c_AH[a];

    const float* cp = cls + cell * 18 + a * 2;
    float s0 = cp[0], s1 = cp[1];
    const float* dp = bbox + cell * 36 + a * 4;
    float dx = dp[0], dy = dp[1], dw = dp[2], dh = dp[3];

    // explicit .rn ops (no FMA contraction; match XLA codegen)
    float pxc = __fadd_rn(__fmul_rn(dx, aw), axc);
    float pyc = __fadd_rn(__fmul_rn(dy, ah), ayc);
    float pw  = __fmul_rn(expf(dw), aw);
    float ph  = __fmul_rn(expf(dh), ah);
    float hx  = __fmul_rn(0.5f, pw);
    float hy  = __fmul_rn(0.5f, ph);
    float x1 = fminf(fmaxf(__fsub_rn(pxc, hx), 0.f), 1023.f);
    float x2 = fminf(fmaxf(__fadd_rn(pxc, hx), 0.f), 1023.f);
    float y1 = fminf(fmaxf(__fsub_rn(pyc, hy), 0.f), 1023.f);
    float y2 = fminf(fmaxf(__fadd_rn(pyc, hy), 0.f), 1023.f);

    bool valid = (__fadd_rn(__fsub_rn(x2, x1), 1.f) >= 16.f) &&
                 (__fadd_rn(__fsub_rn(y2, y1), 1.f) >= 16.f);

    float m  = fmaxf(s0, s1);
    float e0 = expf(__fsub_rn(s0, m));
    float e1 = expf(__fsub_rn(s1, m));
    float sc = __fdiv_rn(e1, __fadd_rn(e0, e1));
    if (!valid) sc = -INFINITY;

    g_pbox[i] = make_float4(x1, y1, x2, y2);

    unsigned ub = __float_as_uint(sc);
    ub = (ub & 0x80000000u) ? ~ub : (ub | 0x80000000u);
    g_skey[i] = ub;
    atomicAdd(&g_hist[ub >> 18], 1);
}

// ------------------------------ 2) threshold + suffix offsets (1 block) ------
__global__ void __launch_bounds__(256, 1) thresh_kernel() {
    int t = threadIdx.x;
    __shared__ int ws[8];
    if (t == 0) atomicAdd(&g_epoch, 1u);     // epoch for the rowdone pipeline

    // chunk t covers bins [lo, lo+63], chunks ordered DESCENDING by bin
    int lo = NBIN - 64 * (t + 1);
    int base4 = lo >> 2;
    int c[64];
    int sum = 0;
    #pragma unroll
    for (int k = 0; k < 16; k++) {
        int4 v = reinterpret_cast<const int4*>(g_hist)[base4 + k];
        c[4*k+0] = v.x; c[4*k+1] = v.y; c[4*k+2] = v.z; c[4*k+3] = v.w;
        sum += v.x + v.y + v.z + v.w;
    }
    int incl = bscan256(sum, t, ws);
    int run = incl - sum;       // anchors in bins strictly above this chunk
    #pragma unroll
    for (int kk = 63; kk >= 0; kk--) {       // descending bins within chunk
        int h = c[kk];
        c[kk] = run;                          // becomes sufx[lo+kk]
        int nrun = run + h;
        if (run < KTOP && nrun >= KTOP) { g_tb = lo + kk; g_S = nrun; }
        run = nrun;
    }
    #pragma unroll
    for (int k = 0; k < 16; k++) {
        reinterpret_cast<int4*>(g_sufx)[base4 + k] =
            make_int4(c[4*k+0], c[4*k+1], c[4*k+2], c[4*k+3]);
    }
}

// ------------------------------ 3) compaction into bin-grouped slots ---------
__global__ void compact_kernel() {
    int i = blockIdx.x * blockDim.x + threadIdx.x;
    if (i >= NPROP) return;
    unsigned key = g_skey[i];
    int bin = (int)(key >> 18);
    if (bin >= g_tb) {
        int pos = g_sufx[bin] + atomicAdd(&g_bcur[bin], 1);
        g_k64[pos] = ((unsigned long long)key << 32) |
                     (unsigned long long)(0xFFFFFFFFu - (unsigned)i);
        g_iS[pos] = i;
    }
}

// ------------------------------ 4) exact rank + scatter ----------------------
__global__ void rankscatter_kernel() {
    int p = blockIdx.x * blockDim.x + threadIdx.x;
    if (p >= g_S) return;
    unsigned long long ki = g_k64[p];
    unsigned bin = (unsigned)(ki >> 50);
    int b0 = g_sufx[bin];
    int nb = g_hist[bin];
    int r = b0;
    for (int m = 0; m < nb; m++) r += (g_k64[b0 + m] > ki);
    if (r < KTOP) {
        float4 f = g_pbox[g_iS[p]];
        g_tbox[r] = f;
        g_ta[r] = __fmul_rn(__fadd_rn(__fsub_rn(f.z, f.x), 1.f),
                            __fadd_rn(__fsub_rn(f.w, f.y), 1.f));
    }
}

// ------------------------------ 5) fused mask producer + greedy scan ---------
__device__ __forceinline__ void load_tile(unsigned (&dst)[32], int t, int T) {
    const uint4* q = reinterpret_cast<const uint4*>(
        &g_maskT[(size_t)t * KPAD + (size_t)T * 32]);
    #pragma unroll
    for (int i = 0; i < 8; i++) {
        uint4 v = q[i];
        dst[4*i+0] = v.x; dst[4*i+1] = v.y; dst[4*i+2] = v.z; dst[4*i+3] = v.w;
    }
}

__device__ __forceinline__ unsigned or_sel(const unsigned (&w)[32], unsigned km) {
    unsigned a0 = 0, a1 = 0, a2 = 0, a3 = 0;
    #pragma unroll
    for (int b = 0; b < 32; b += 4) {
        if (km & (1u << b))       a0 |= w[b];
        if (km & (1u << (b + 1))) a1 |= w[b + 1];
        if (km & (1u << (b + 2))) a2 |= w[b + 2];
        if (km & (1u << (b + 3))) a3 |= w[b + 3];
    }
    return (a0 | a1) | (a2 | a3);
}

__device__ __forceinline__ void diag_resolve(const unsigned (&D)[32], unsigned removed,
                                             unsigned& kept_out) {
    unsigned internal = removed, kept = 0u;
    #pragma unroll
    for (int b = 0; b < 32; b++) {
        if (!((internal >> b) & 1u)) { kept |= (1u << b); internal |= D[b]; }
    }
    kept_out = kept;
}

__global__ void __launch_bounds__(256, 2) maskscan_kernel(float* __restrict__ out) {
    const int t = threadIdx.x;
    __shared__ float4 sb[32];
    __shared__ float sa[32];
    __shared__ int s_ws[8];
    __shared__ unsigned s_keep[2];
    __shared__ int s_tot[2];
    __shared__ int s_sidx[NOUT];
    __shared__ int s_C;

    if (blockIdx.x != 0) {
        // =================== mask producer blocks ===================
        int nbk = gridDim.x - 1;
        for (int m = (int)blockIdx.x - 1; m < NRB * WORDS; m += nbk) {
            int rb = m / WORDS;
            int wx = m - rb * WORDS;
            if (wx >= 8 * rb) {                 // tile touches upper triangle
                __syncthreads();
                if (t < 32) {
                    int c = wx * 32 + t;
                    sb[t] = g_tbox[c];
                    sa[t] = g_ta[c];
                }
                __syncthreads();
                int r = rb * 256 + t;

                int cbase = wx * 32;
                unsigned mgt;
                if (r < cbase) mgt = 0xFFFFFFFFu;
                else { int d = r - cbase; mgt = (d >= 31) ? 0u : ~((2u << d) - 1u); }
                unsigned mlt = (wx == WORDS - 1) ? 0xFFFFu : 0xFFFFFFFFu;
                unsigned cmask = mgt & mlt;

                unsigned w = 0;
                if (r < KTOP && cmask) {
                    float4 rbx = g_tbox[r];
                    float ar = g_ta[r];
                    #pragma unroll
                    for (int b = 0; b < 32; b++) {
                        float4 cb = sb[b];
                        float ca = sa[b];
                        float ix1 = fmaxf(rbx.x, cb.x);
                        float iy1 = fmaxf(rbx.y, cb.y);
                        float ix2 = fminf(rbx.z, cb.z);
                        float iy2 = fminf(rbx.w, cb.w);
                        float iw = fmaxf(__fadd_rn(__fsub_rn(ix2, ix1), 1.f), 0.f);
                        float ih = fmaxf(__fadd_rn(__fsub_rn(iy2, iy1), 1.f), 0.f);
                        float inter = __fmul_rn(iw, ih);
                        float uni = __fsub_rn(__fadd_rn(ar, ca), inter);
                        float iou = __fdiv_rn(inter, uni);
                        if (iou > 0.7f) w |= (1u << b);
                    }
                    w &= cmask;
                }
                if (r < KPAD) g_maskT[(size_t)wx * KPAD + r] = w;
                __threadfence();
            }
            __syncthreads();
            if (t == 0) atomicAdd(&g_rowdone[rb], 1u);
        }
        // rezero hist/bcur for the NEXT graph replay
        int gt = ((int)blockIdx.x - 1) * 256 + t;
        int gs = nbk * 256;
        for (int i = gt; i < NBIN; i += gs) { g_hist[i] = 0; g_bcur[i] = 0; }
        return;
    }

    // =================== block 0: pipelined greedy scan ===================
    unsigned epoch = atomicAdd(&g_epoch, 0u);
    unsigned want = 188u * epoch;
    int rbdone = -1;                  // meaningful on thread 0 only
    bool act = (t < WORDS);
    bool dload = false;
    unsigned D[32], Abuf[32], Bbuf[32];
    unsigned removed = 0;
    int stop = TILES - 1;

    // wait rows for tile 0 + first D window (tiles <= 7 -> rb 0)
    if (t == 0) {
        while (rbdone < 0) {
            if (atomicAdd(&g_rowdone[0], 0u) >= want) rbdone = 0;
        }
        __threadfence();
    }
    __syncthreads();
    if (act && t >= 1) load_tile(Abuf, t, 0);

    #pragma unroll 1
    for (int T = 0; T < TILES; T += 2) {
        // rows needed this pair: loads of tiles <= T+2, D-prefetch tiles <= T+7
        int need = (T + 7) >> 3;
        if (need > NRB - 1) need = NRB - 1;
        if (t == 0 && rbdone < need) {
            while (rbdone < need) {
                if (atomicAdd(&g_rowdone[rbdone + 1], 0u) >= want) rbdone++;
            }
            __threadfence();
        }
        __syncthreads();
        if (act && !dload && t <= T + 7) { load_tile(D, t, t); dload = true; }

        // ---- even tile T ----
        if (act && t >= T + 2 && T + 1 < TILES) load_tile(Bbuf, t, T + 1);
        if (t == T) {
            unsigned kept;
            diag_resolve(D, removed, kept);
            s_keep[0] = kept;
            unsigned cv = (T == TILES - 1) ? (kept & 0xFFFFu) : kept;
            s_tot[0] = ((T == 0) ? 0 : s_tot[1]) + __popc(cv);
        }
        __syncthreads();
        {
            unsigned km = s_keep[0];
            if (act && t >= T) {
                if (t == T) removed |= or_sel(D, km);
                else        removed |= or_sel(Abuf, km);
            }
            if (s_tot[0] >= NOUT) { stop = T; break; }
        }
        // ---- odd tile T+1 ----
        if (T + 1 < TILES) {
            if (act && t >= T + 3 && T + 2 < TILES) load_tile(Abuf, t, T + 2);
            if (t == T + 1) {
                unsigned kept;
                diag_resolve(D, removed, kept);
                s_keep[1] = kept;
                unsigned cv = (T + 1 == TILES - 1) ? (kept & 0xFFFFu) : kept;
                s_tot[1] = s_tot[0] + __popc(cv);
            }
            __syncthreads();
            unsigned km = s_keep[1];
            if (act && t >= T + 1) {
                if (t == T + 1) removed |= or_sel(D, km);
                else            removed |= or_sel(Bbuf, km);
            }
            if (s_tot[1] >= NOUT) { stop = T + 1; break; }
        }
    }
    __syncthreads();

    // ---- select first 300 + output ----
    int L = min(KTOP, 32 * (stop + 1));
    int nb = L - 32 * t;
    nb = nb < 0 ? 0 : (nb > 32 ? 32 : nb);
    unsigned vmask = (nb >= 32) ? 0xFFFFFFFFu : ((nb > 0) ? ((1u << nb) - 1u) : 0u);

    unsigned rem = act ? removed : 0u;
    unsigned kept = (~rem) & vmask;
    int cnt = __popc(kept);
    int incl = bscan256(cnt, t, s_ws);
    int excl = incl - cnt;
    if (t == 255) s_C = incl;
    __syncthreads();
    int C = s_C;

    if (excl < NOUT && kept) {
        int r = excl;
        #pragma unroll 4
        for (int b = 0; b < 32; b++) {
            if ((kept >> b) & 1u) {
                if (r < NOUT) s_sidx[r] = t * 32 + b;
                r++;
            }
        }
    }
    __syncthreads();

    if (C < NOUT) {   // fill with suppressed (index ascending)
        unsigned sup = rem & vmask;
        int cnt2 = __popc(sup);
        int incl2 = bscan256(cnt2, t, s_ws);
        int b0 = C + (incl2 - cnt2);
        if (b0 < NOUT && sup) {
            #pragma unroll 4
            for (int b = 0; b < 32; b++) {
                if ((sup >> b) & 1u) {
                    if (b0 < NOUT) s_sidx[b0] = t * 32 + b;
                    b0++;
                }
            }
        }
        __syncthreads();
    }

    for (int r = t; r < NOUT; r += 256) {
        int idx = s_sidx[r];
        float4 f = g_tbox[idx];
        out[5 * r + 0] = 0.f;
        out[5 * r + 1] = f.x;
        out[5 * r + 2] = f.y;
        out[5 * r + 3] = f.z;
        out[5 * r + 4] = f.w;
    }
}

// ------------------------------ launch ---------------------------------------
extern "C" void kernel_launch(void* const* d_in, const int* in_sizes, int n_in,
                              void* d_out, int out_size) {
    const float* cls  = (const float*)d_in[0];   // (1,64,64,18)
    const float* bbox = (const float*)d_in[1];   // (1,64,64,36)
    float* out = (float*)d_out;                  // (300,5)

    int dev = 0;
    cudaGetDevice(&dev);
    int sms = 0;
    cudaDeviceGetAttribute(&sms, cudaDevAttrMultiProcessorCount, dev);
    int occ = 0;
    cudaOccupancyMaxActiveBlocksPerMultiprocessor(&occ, maskscan_kernel, 256, 0);
    if (occ < 1) occ = 1;
    if (occ > 2) occ = 2;
    int G = sms * occ;     // all co-resident: producer/consumer pipeline is safe

    proposal_kernel<<<NPROP / 256, 256>>>(cls, bbox);
    thresh_kernel<<<1, 256>>>();
    compact_kernel<<<NPROP / 256, 256>>>();
    rankscatter_kernel<<<NPROP / 256, 256>>>();
    maskscan_kernel<<<G, 256>>>(out);
}

// round 14
// speedup vs baseline: 1.2326x; 1.0417x over previous
#include <cuda_runtime.h>
#include <cuda_bf16.h>
#include <cstdint>
#include <math.h>

// ---------------------------------------------------------------------------
// RoiProposal: 6 kernels.
//  proposal(+hist) -> thresh -> compact -> rankscatter(MLP) ->
//  mask(+rezero tail) -> scan+out
// ---------------------------------------------------------------------------

#define NPROP 36864
#define KTOP  6000
#define KPAD  6016
#define WORDS 188
#define TILES 188
#define NOUT  300
#define NBIN  16384      // histogram bins (key >> 18)

// ------------------------------ scratch --------------------------------------
// NOTE: device globals are zero-initialized at module load; g_hist/g_bcur are
// re-zeroed at the tail of mask_kernel so every graph replay starts clean.
__device__ unsigned g_skey[NPROP];
__device__ __align__(16) int g_hist[NBIN];
__device__ int g_bcur[NBIN];
__device__ __align__(16) int g_sufx[NBIN];
__device__ int g_tb, g_S;
__device__ unsigned long long g_k64[NPROP];     // survivors, bin-grouped
__device__ int g_iS[NPROP];
__device__ float4 g_pbox[NPROP];
__device__ float4 g_tbox[KPAD];
__device__ float  g_ta[KPAD];
__device__ unsigned g_maskT[(size_t)WORDS * KPAD];   // [word][row]

__constant__ float c_AW[9] = {184.f, 368.f, 736.f, 128.f, 256.f, 512.f, 88.f, 176.f, 352.f};
__constant__ float c_AH[9] = {96.f, 192.f, 384.f, 128.f, 256.f, 512.f, 176.f, 352.f, 704.f};

// ------------------------------ 256-thread inclusive scan --------------------
__device__ __forceinline__ int bscan256(int v, int t, int* ws) {
    #pragma unroll
    for (int d = 1; d < 32; d <<= 1) {
        int n = __shfl_up_sync(0xFFFFFFFFu, v, d);
        if ((t & 31) >= d) v += n;
    }
    if ((t & 31) == 31) ws[t >> 5] = v;
    __syncthreads();
    if (t < 32) {
        int w = (t < 8) ? ws[t] : 0;
        #pragma unroll
        for (int d = 1; d < 8; d <<= 1) {
            int n = __shfl_up_sync(0xFFFFFFFFu, w, d);
            if (t >= d) w += n;
        }
        if (t < 8) ws[t] = w;
    }
    __syncthreads();
    if (t >= 32) v += ws[(t >> 5) - 1];
    __syncthreads();
    return v;
}

// ------------------------------ 1) proposals + keys + histogram --------------
__global__ void proposal_kernel(const float* __restrict__ cls,
                                const float* __restrict__ bbox) {
    int i = blockIdx.x * blockDim.x + threadIdx.x;
    if (i >= NPROP) return;

    int a = i % 9;
    int cell = i / 9;
    float axc = (float)((cell % 64) * 16 + 8);
    float ayc = (float)((cell / 64) * 16 + 8);
    float aw = c_AW[a];
    float ah = c_AH[a];

    const float* cp = cls + cell * 18 + a * 2;
    float s0 = cp[0], s1 = cp[1];
    const float* dp = bbox + cell * 36 + a * 4;
    float dx = dp[0], dy = dp[1], dw = dp[2], dh = dp[3];

    // explicit .rn ops (no FMA contraction; match XLA codegen)
    float pxc = __fadd_rn(__fmul_rn(dx, aw), axc);
    float pyc = __fadd_rn(__fmul_rn(dy, ah), ayc);
    float pw  = __fmul_rn(expf(dw), aw);
    float ph  = __fmul_rn(expf(dh), ah);
    float hx  = __fmul_rn(0.5f, pw);
    float hy  = __fmul_rn(0.5f, ph);
    float x1 = fminf(fmaxf(__fsub_rn(pxc, hx), 0.f), 1023.f);
    float x2 = fminf(fmaxf(__fadd_rn(pxc, hx), 0.f), 1023.f);
    float y1 = fminf(fmaxf(__fsub_rn(pyc, hy), 0.f), 1023.f);
    float y2 = fminf(fmaxf(__fadd_rn(pyc, hy), 0.f), 1023.f);

    bool valid = (__fadd_rn(__fsub_rn(x2, x1), 1.f) >= 16.f) &&
                 (__fadd_rn(__fsub_rn(y2, y1), 1.f) >= 16.f);

    float m  = fmaxf(s0, s1);
    float e0 = expf(__fsub_rn(s0, m));
    float e1 = expf(__fsub_rn(s1, m));
    float sc = __fdiv_rn(e1, __fadd_rn(e0, e1));
    if (!valid) sc = -INFINITY;

    g_pbox[i] = make_float4(x1, y1, x2, y2);

    unsigned ub = __float_as_uint(sc);
    ub = (ub & 0x80000000u) ? ~ub : (ub | 0x80000000u);
    g_skey[i] = ub;
    atomicAdd(&g_hist[ub >> 18], 1);
}

// ------------------------------ 2) threshold + suffix offsets (1 block) ------
__global__ void __launch_bounds__(256, 1) thresh_kernel() {
    int t = threadIdx.x;
    __shared__ int ws[8];

    // chunk t covers bins [lo, lo+63], chunks ordered DESCENDING by bin
    int lo = NBIN - 64 * (t + 1);
    int base4 = lo >> 2;
    int c[64];
    int sum = 0;
    #pragma unroll
    for (int k = 0; k < 16; k++) {
        int4 v = reinterpret_cast<const int4*>(g_hist)[base4 + k];
        c[4*k+0] = v.x; c[4*k+1] = v.y; c[4*k+2] = v.z; c[4*k+3] = v.w;
        sum += v.x + v.y + v.z + v.w;
    }
    int incl = bscan256(sum, t, ws);
    int run = incl - sum;       // anchors in bins strictly above this chunk
    #pragma unroll
    for (int kk = 63; kk >= 0; kk--) {       // descending bins within chunk
        int h = c[kk];
        c[kk] = run;                          // becomes sufx[lo+kk]
        int nrun = run + h;
        if (run < KTOP && nrun >= KTOP) { g_tb = lo + kk; g_S = nrun; }
        run = nrun;
    }
    #pragma unroll
    for (int k = 0; k < 16; k++) {
        reinterpret_cast<int4*>(g_sufx)[base4 + k] =
            make_int4(c[4*k+0], c[4*k+1], c[4*k+2], c[4*k+3]);
    }
}

// ------------------------------ 3) compaction into bin-grouped slots ---------
__global__ void compact_kernel() {
    int i = blockIdx.x * blockDim.x + threadIdx.x;
    if (i >= NPROP) return;
    unsigned key = g_skey[i];
    int bin = (int)(key >> 18);
    if (bin >= g_tb) {
        int pos = g_sufx[bin] + atomicAdd(&g_bcur[bin], 1);
        g_k64[pos] = ((unsigned long long)key << 32) |
                     (unsigned long long)(0xFFFFFFFFu - (unsigned)i);
        g_iS[pos] = i;
    }
}

// ------------------------------ 4) exact rank + scatter (MLP loop) -----------
// rank = sufx[bin] + #{same-bin j : k64_j > k64_i}. Unique u64 keys encode
// (score desc, idx asc) -> exact jax top_k order. Singleton bins: no key loads.
__global__ void rankscatter_kernel() {
    int p = blockIdx.x * blockDim.x + threadIdx.x;
    if (p >= g_S) return;
    unsigned long long ki = g_k64[p];
    unsigned bin = (unsigned)(ki >> 50);
    int b0 = g_sufx[bin];
    int nb = g_hist[bin];
    int r = b0;
    if (nb > 1) {
        // 4-wide predicated batches: 4 independent loads in flight
        for (int m = 0; m < nb; m += 4) {
            unsigned long long a0 = (m + 0 < nb) ? g_k64[b0 + m + 0] : 0ull;
            unsigned long long a1 = (m + 1 < nb) ? g_k64[b0 + m + 1] : 0ull;
            unsigned long long a2 = (m + 2 < nb) ? g_k64[b0 + m + 2] : 0ull;
            unsigned long long a3 = (m + 3 < nb) ? g_k64[b0 + m + 3] : 0ull;
            r += (int)(a0 > ki) + (int)(a1 > ki) + (int)(a2 > ki) + (int)(a3 > ki);
        }
    }
    if (r < KTOP) {
        float4 f = g_pbox[g_iS[p]];
        g_tbox[r] = f;
        g_ta[r] = __fmul_rn(__fadd_rn(__fsub_rn(f.z, f.x), 1.f),
                            __fadd_rn(__fsub_rn(f.w, f.y), 1.f));
    }
}

// ------------------------------ 5) IoU suppression bitmask + rezero tail -----
__global__ void mask_kernel() {
    int wx = blockIdx.x;                       // 0..187
    int tid = threadIdx.x;
    // tail duty: rezero hist/bcur for the NEXT graph replay (stream-ordered)
    int gz = wx * (int)blockDim.x + tid;       // covers 188*128 > 16384
    bool dozero = (gz < NBIN);

    if (wx >= 4 * (int)blockIdx.y) {           // tile touches upper triangle
        int r = blockIdx.y * 128 + tid;        // 0..6015
        __shared__ float4 sb[32];
        __shared__ float sa[32];
        if (tid < 32) {
            int c = wx * 32 + tid;
            sb[tid] = g_tbox[c];
            sa[tid] = g_ta[c];
        }
        __syncthreads();

        int cbase = wx * 32;
        unsigned mgt;
        if (r < cbase) mgt = 0xFFFFFFFFu;
        else { int d = r - cbase; mgt = (d >= 31) ? 0u : ~((2u << d) - 1u); }
        unsigned mlt = (wx == WORDS - 1) ? 0xFFFFu : 0xFFFFFFFFu;
        unsigned cmask = mgt & mlt;

        unsigned w = 0;
        if (r < KTOP && cmask) {
            float4 rbx = g_tbox[r];
            float ar = g_ta[r];
            #pragma unroll
            for (int b = 0; b < 32; b++) {
                float4 cb = sb[b];
                float ca = sa[b];
                float ix1 = fmaxf(rbx.x, cb.x);
                float iy1 = fmaxf(rbx.y, cb.y);
                float ix2 = fminf(rbx.z, cb.z);
                float iy2 = fminf(rbx.w, cb.w);
                float iw = fmaxf(__fadd_rn(__fsub_rn(ix2, ix1), 1.f), 0.f);
                float ih = fmaxf(__fadd_rn(__fsub_rn(iy2, iy1), 1.f), 0.f);
                float inter = __fmul_rn(iw, ih);
                float uni = __fsub_rn(__fadd_rn(ar, ca), inter);
                float iou = __fdiv_rn(inter, uni);
                if (iou > 0.7f) w |= (1u << b);
            }
            w &= cmask;
        }
        if (r < KPAD) g_maskT[(size_t)wx * KPAD + r] = w;
    }
    // rezero (only y-slice 0 does it, once per wx-column of blocks)
    if (blockIdx.y == 0 && dozero) { g_hist[gz] = 0; g_bcur[gz] = 0; }
}

// ------------------------------ 6) greedy NMS scan + select + output ---------
__device__ __forceinline__ void load_tile(unsigned (&dst)[32], int t, int T) {
    const uint4* q = reinterpret_cast<const uint4*>(
        &g_maskT[(size_t)t * KPAD + (size_t)T * 32]);
    #pragma unroll
    for (int i = 0; i < 8; i++) {
        uint4 v = q[i];
        dst[4*i+0] = v.x; dst[4*i+1] = v.y; dst[4*i+2] = v.z; dst[4*i+3] = v.w;
    }
}

__device__ __forceinline__ unsigned or_sel(const unsigned (&w)[32], unsigned km) {
    unsigned a0 = 0, a1 = 0, a2 = 0, a3 = 0;
    #pragma unroll
    for (int b = 0; b < 32; b += 4) {
        if (km & (1u << b))       a0 |= w[b];
        if (km & (1u << (b + 1))) a1 |= w[b + 1];
        if (km & (1u << (b + 2))) a2 |= w[b + 2];
        if (km & (1u << (b + 3))) a3 |= w[b + 3];
    }
    return (a0 | a1) | (a2 | a3);
}

__device__ __forceinline__ void diag_resolve(const unsigned (&D)[32], unsigned removed,
                                             unsigned& kept_out) {
    unsigned internal = removed, kept = 0u;
    #pragma unroll
    for (int b = 0; b < 32; b++) {
        if (!((internal >> b) & 1u)) { kept |= (1u << b); internal |= D[b]; }
    }
    kept_out = kept;
}

__global__ void __launch_bounds__(256, 1) scan_out_kernel(float* __restrict__ out) {
    const int t = threadIdx.x;
    __shared__ int s_ws[8];
    __shared__ unsigned s_keep[2];
    __shared__ int s_tot[2];
    __shared__ int s_sidx[NOUT];
    __shared__ int s_C;

    bool act = (t < WORDS);
    unsigned D[32], Abuf[32], Bbuf[32];
    unsigned removed = 0;
    int stop = TILES - 1;

    if (act) load_tile(D, t, t);
    if (act && t >= 1) load_tile(Abuf, t, 0);

    #pragma unroll 1
    for (int T = 0; T < TILES; T += 2) {
        if (act && t >= T + 2 && T + 1 < TILES) load_tile(Bbuf, t, T + 1);
        if (t == T) {
            unsigned kept;
            diag_resolve(D, removed, kept);
            s_keep[0] = kept;
            unsigned cv = (T == TILES - 1) ? (kept & 0xFFFFu) : kept;
            s_tot[0] = ((T == 0) ? 0 : s_tot[1]) + __popc(cv);
        }
        __syncthreads();
        {
            unsigned km = s_keep[0];
            if (act && t >= T) {
                if (t == T) removed |= or_sel(D, km);
                else        removed |= or_sel(Abuf, km);
            }
            if (s_tot[0] >= NOUT) { stop = T; break; }
        }
        if (T + 1 < TILES) {
            if (act && t >= T + 3 && T + 2 < TILES) load_tile(Abuf, t, T + 2);
            if (t == T + 1) {
                unsigned kept;
                diag_resolve(D, removed, kept);
                s_keep[1] = kept;
                unsigned cv = (T + 1 == TILES - 1) ? (kept & 0xFFFFu) : kept;
                s_tot[1] = s_tot[0] + __popc(cv);
            }
            __syncthreads();
            unsigned km = s_keep[1];
            if (act && t >= T + 1) {
                if (t == T + 1) removed |= or_sel(D, km);
                else            removed |= or_sel(Bbuf, km);
            }
            if (s_tot[1] >= NOUT) { stop = T + 1; break; }
        }
    }
    __syncthreads();

    // ---- select first 300 + output ----
    int L = min(KTOP, 32 * (stop + 1));
    int nb = L - 32 * t;
    nb = nb < 0 ? 0 : (nb > 32 ? 32 : nb);
    unsigned vmask = (nb >= 32) ? 0xFFFFFFFFu : ((nb > 0) ? ((1u << nb) - 1u) : 0u);

    unsigned rem = act ? removed : 0u;
    unsigned kept = (~rem) & vmask;
    int cnt = __popc(kept);
    int incl = bscan256(cnt, t, s_ws);
    int excl = incl - cnt;
    if (t == 255) s_C = incl;
    __syncthreads();
    int C = s_C;

    if (excl < NOUT && kept) {
        int r = excl;
        #pragma unroll 4
        for (int b = 0; b < 32; b++) {
            if ((kept >> b) & 1u) {
                if (r < NOUT) s_sidx[r] = t * 32 + b;
                r++;
            }
        }
    }
    __syncthreads();

    if (C < NOUT) {   // fill with suppressed (index ascending)
        unsigned sup = rem & vmask;
        int cnt2 = __popc(sup);
        int incl2 = bscan256(cnt2, t, s_ws);
        int b0 = C + (incl2 - cnt2);
        if (b0 < NOUT && sup) {
            #pragma unroll 4
            for (int b = 0; b < 32; b++) {
                if ((sup >> b) & 1u) {
                    if (b0 < NOUT) s_sidx[b0] = t * 32 + b;
                    b0++;
                }
            }
        }
        __syncthreads();
    }

    for (int r = t; r < NOUT; r += 256) {
        int idx = s_sidx[r];
        float4 f = g_tbox[idx];
        out[5 * r + 0] = 0.f;
        out[5 * r + 1] = f.x;
        out[5 * r + 2] = f.y;
        out[5 * r + 3] = f.z;
        out[5 * r + 4] = f.w;
    }
}

// ------------------------------ launch ---------------------------------------
extern "C" void kernel_launch(void* const* d_in, const int* in_sizes, int n_in,
                              void* d_out, int out_size) {
    const float* cls  = (const float*)d_in[0];   // (1,64,64,18)
    const float* bbox = (const float*)d_in[1];   // (1,64,64,36)
    float* out = (float*)d_out;                  // (300,5)

    proposal_kernel<<<NPROP / 256, 256>>>(cls, bbox);
    thresh_kernel<<<1, 256>>>();
    compact_kernel<<<NPROP / 256, 256>>>();
    rankscatter_kernel<<<NPROP / 256, 256>>>();
    dim3 mg(WORDS, KPAD / 128);
    mask_kernel<<<mg, 128>>>();
    scan_out_kernel<<<1, 256>>>(out);
}

// round 15
// speedup vs baseline: 1.7227x; 1.3977x over previous
#include <cuda_runtime.h>
#include <cuda_bf16.h>
#include <cstdint>
#include <math.h>

// ---------------------------------------------------------------------------
// RoiProposal: 6 kernels.
//  proposal(+hist) -> thresh -> compact -> rankscatter ->
//  mask(fast-div + rezero tail) -> scan+out
// ---------------------------------------------------------------------------

#define NPROP 36864
#define KTOP  6000
#define KPAD  6016
#define WORDS 188
#define TILES 188
#define NOUT  300
#define NBIN  16384      // histogram bins (key >> 18)

// ------------------------------ scratch --------------------------------------
// Device globals are zero-initialized at module load; g_hist/g_bcur are
// re-zeroed at the tail of mask_kernel so every graph replay starts clean.
__device__ unsigned g_skey[NPROP];
__device__ __align__(16) int g_hist[NBIN];
__device__ int g_bcur[NBIN];
__device__ __align__(16) int g_sufx[NBIN];
__device__ int g_tb, g_S;
__device__ unsigned long long g_k64[NPROP];     // survivors, bin-grouped
__device__ int g_iS[NPROP];
__device__ float4 g_pbox[NPROP];
__device__ float4 g_tbox[KPAD];
__device__ float  g_ta[KPAD];
__device__ unsigned g_maskT[(size_t)WORDS * KPAD];   // [word][row]

__constant__ float c_AW[9] = {184.f, 368.f, 736.f, 128.f, 256.f, 512.f, 88.f, 176.f, 352.f};
__constant__ float c_AH[9] = {96.f, 192.f, 384.f, 128.f, 256.f, 512.f, 176.f, 352.f, 704.f};

// ------------------------------ 256-thread inclusive scan --------------------
__device__ __forceinline__ int bscan256(int v, int t, int* ws) {
    #pragma unroll
    for (int d = 1; d < 32; d <<= 1) {
        int n = __shfl_up_sync(0xFFFFFFFFu, v, d);
        if ((t & 31) >= d) v += n;
    }
    if ((t & 31) == 31) ws[t >> 5] = v;
    __syncthreads();
    if (t < 32) {
        int w = (t < 8) ? ws[t] : 0;
        #pragma unroll
        for (int d = 1; d < 8; d <<= 1) {
            int n = __shfl_up_sync(0xFFFFFFFFu, w, d);
            if (t >= d) w += n;
        }
        if (t < 8) ws[t] = w;
    }
    __syncthreads();
    if (t >= 32) v += ws[(t >> 5) - 1];
    __syncthreads();
    return v;
}

// ------------------------------ 1) proposals + keys + histogram --------------
__global__ void proposal_kernel(const float* __restrict__ cls,
                                const float* __restrict__ bbox) {
    int i = blockIdx.x * blockDim.x + threadIdx.x;
    if (i >= NPROP) return;

    int a = i % 9;
    int cell = i / 9;
    float axc = (float)((cell % 64) * 16 + 8);
    float ayc = (float)((cell / 64) * 16 + 8);
    float aw = c_AW[a];
    float ah = c_AH[a];

    const float* cp = cls + cell * 18 + a * 2;
    float s0 = cp[0], s1 = cp[1];
    const float* dp = bbox + cell * 36 + a * 4;
    float dx = dp[0], dy = dp[1], dw = dp[2], dh = dp[3];

    // explicit .rn ops (no FMA contraction; match XLA codegen)
    float pxc = __fadd_rn(__fmul_rn(dx, aw), axc);
    float pyc = __fadd_rn(__fmul_rn(dy, ah), ayc);
    float pw  = __fmul_rn(expf(dw), aw);
    float ph  = __fmul_rn(expf(dh), ah);
    float hx  = __fmul_rn(0.5f, pw);
    float hy  = __fmul_rn(0.5f, ph);
    float x1 = fminf(fmaxf(__fsub_rn(pxc, hx), 0.f), 1023.f);
    float x2 = fminf(fmaxf(__fadd_rn(pxc, hx), 0.f), 1023.f);
    float y1 = fminf(fmaxf(__fsub_rn(pyc, hy), 0.f), 1023.f);
    float y2 = fminf(fmaxf(__fadd_rn(pyc, hy), 0.f), 1023.f);

    bool valid = (__fadd_rn(__fsub_rn(x2, x1), 1.f) >= 16.f) &&
                 (__fadd_rn(__fsub_rn(y2, y1), 1.f) >= 16.f);

    float m  = fmaxf(s0, s1);
    float e0 = expf(__fsub_rn(s0, m));
    float e1 = expf(__fsub_rn(s1, m));
    float sc = __fdiv_rn(e1, __fadd_rn(e0, e1));
    if (!valid) sc = -INFINITY;

    g_pbox[i] = make_float4(x1, y1, x2, y2);

    unsigned ub = __float_as_uint(sc);
    ub = (ub & 0x80000000u) ? ~ub : (ub | 0x80000000u);
    g_skey[i] = ub;
    atomicAdd(&g_hist[ub >> 18], 1);
}

// ------------------------------ 2) threshold + suffix offsets (1 block) ------
__global__ void __launch_bounds__(256, 1) thresh_kernel() {
    int t = threadIdx.x;
    __shared__ int ws[8];

    // chunk t covers bins [lo, lo+63], chunks ordered DESCENDING by bin
    int lo = NBIN - 64 * (t + 1);
    int base4 = lo >> 2;
    int c[64];
    int sum = 0;
    #pragma unroll
    for (int k = 0; k < 16; k++) {
        int4 v = reinterpret_cast<const int4*>(g_hist)[base4 + k];
        c[4*k+0] = v.x; c[4*k+1] = v.y; c[4*k+2] = v.z; c[4*k+3] = v.w;
        sum += v.x + v.y + v.z + v.w;
    }
    int incl = bscan256(sum, t, ws);
    int run = incl - sum;       // anchors in bins strictly above this chunk
    #pragma unroll
    for (int kk = 63; kk >= 0; kk--) {       // descending bins within chunk
        int h = c[kk];
        c[kk] = run;                          // becomes sufx[lo+kk]
        int nrun = run + h;
        if (run < KTOP && nrun >= KTOP) { g_tb = lo + kk; g_S = nrun; }
        run = nrun;
    }
    #pragma unroll
    for (int k = 0; k < 16; k++) {
        reinterpret_cast<int4*>(g_sufx)[base4 + k] =
            make_int4(c[4*k+0], c[4*k+1], c[4*k+2], c[4*k+3]);
    }
}

// ------------------------------ 3) compaction into bin-grouped slots ---------
__global__ void compact_kernel() {
    int i = blockIdx.x * blockDim.x + threadIdx.x;
    if (i >= NPROP) return;
    unsigned key = g_skey[i];
    int bin = (int)(key >> 18);
    if (bin >= g_tb) {
        int pos = g_sufx[bin] + atomicAdd(&g_bcur[bin], 1);
        g_k64[pos] = ((unsigned long long)key << 32) |
                     (unsigned long long)(0xFFFFFFFFu - (unsigned)i);
        g_iS[pos] = i;
    }
}

// ------------------------------ 4) exact rank + scatter ----------------------
// rank = sufx[bin] + #{same-bin j : k64_j > k64_i}. Unique u64 keys encode
// (score desc, idx asc) -> exact jax top_k order. Singleton bins: no key loads.
__global__ void rankscatter_kernel() {
    int p = blockIdx.x * blockDim.x + threadIdx.x;
    if (p >= g_S) return;
    unsigned long long ki = g_k64[p];
    unsigned bin = (unsigned)(ki >> 50);
    int b0 = g_sufx[bin];
    int nb = g_hist[bin];
    int r = b0;
    if (nb > 1) {
        for (int m = 0; m < nb; m++) r += (g_k64[b0 + m] > ki);
    }
    if (r < KTOP) {
        float4 f = g_pbox[g_iS[p]];
        g_tbox[r] = f;
        g_ta[r] = __fmul_rn(__fadd_rn(__fsub_rn(f.z, f.x), 1.f),
                            __fadd_rn(__fsub_rn(f.w, f.y), 1.f));
    }
}

// ------------------------------ 5) IoU bitmask (guarded fast divide) ---------
// Decision rn(inter/uni) > 0.7: when |inter - 0.7*uni| > 1e-5*uni the float
// fast expression's sign provably matches (margin >> fp32 rounding of the
// fast path AND of the correctly-rounded divide); boundary/degenerate cases
// take the exact __fdiv_rn fallback. Bit-identical to the reference.
__global__ void mask_kernel() {
    int wx = blockIdx.x;                       // 0..187
    int tid = threadIdx.x;
    int gz = wx * (int)blockDim.x + tid;       // rezero index (188*128 > 16384)

    if (wx >= 4 * (int)blockIdx.y) {           // tile touches upper triangle
        int r = blockIdx.y * 128 + tid;        // 0..6015
        __shared__ float4 sb[32];
        __shared__ float sa[32];
        if (tid < 32) {
            int c = wx * 32 + tid;
            sb[tid] = g_tbox[c];
            sa[tid] = g_ta[c];
        }
        __syncthreads();

        int cbase = wx * 32;
        unsigned mgt;
        if (r < cbase) mgt = 0xFFFFFFFFu;
        else { int d = r - cbase; mgt = (d >= 31) ? 0u : ~((2u << d) - 1u); }
        unsigned mlt = (wx == WORDS - 1) ? 0xFFFFu : 0xFFFFFFFFu;
        unsigned cmask = mgt & mlt;

        unsigned w = 0;
        if (r < KTOP && cmask) {
            float4 rbx = g_tbox[r];
            float ar = g_ta[r];
            #pragma unroll
            for (int b = 0; b < 32; b++) {
                float4 cb = sb[b];
                float ca = sa[b];
                float ix1 = fmaxf(rbx.x, cb.x);
                float iy1 = fmaxf(rbx.y, cb.y);
                float ix2 = fminf(rbx.z, cb.z);
                float iy2 = fminf(rbx.w, cb.w);
                float iw = fmaxf(__fadd_rn(__fsub_rn(ix2, ix1), 1.f), 0.f);
                float ih = fmaxf(__fadd_rn(__fsub_rn(iy2, iy1), 1.f), 0.f);
                float inter = __fmul_rn(iw, ih);
                float uni = __fsub_rn(__fadd_rn(ar, ca), inter);
                float d = __fmaf_rn(-0.7f, uni, inter);   // fast-path slack
                bool bit;
                if (uni > 0.f && fabsf(d) > 1e-5f * uni) {
                    bit = (d > 0.f);
                } else {
                    bit = (__fdiv_rn(inter, uni) > 0.7f); // exact fallback
                }
                if (bit) w |= (1u << b);
            }
            w &= cmask;
        }
        if (r < KPAD) g_maskT[(size_t)wx * KPAD + r] = w;
    }
    // rezero hist/bcur for the NEXT graph replay (stream-ordered wrt replay)
    if (blockIdx.y == 0 && gz < NBIN) { g_hist[gz] = 0; g_bcur[gz] = 0; }
}

// ------------------------------ 6) greedy NMS scan + select + output ---------
__device__ __forceinline__ void load_tile(unsigned (&dst)[32], int t, int T) {
    const uint4* q = reinterpret_cast<const uint4*>(
        &g_maskT[(size_t)t * KPAD + (size_t)T * 32]);
    #pragma unroll
    for (int i = 0; i < 8; i++) {
        uint4 v = q[i];
        dst[4*i+0] = v.x; dst[4*i+1] = v.y; dst[4*i+2] = v.z; dst[4*i+3] = v.w;
    }
}

__device__ __forceinline__ unsigned or_sel(const unsigned (&w)[32], unsigned km) {
    unsigned a0 = 0, a1 = 0, a2 = 0, a3 = 0;
    #pragma unroll
    for (int b = 0; b < 32; b += 4) {
        if (km & (1u << b))       a0 |= w[b];
        if (km & (1u << (b + 1))) a1 |= w[b + 1];
        if (km & (1u << (b + 2))) a2 |= w[b + 2];
        if (km & (1u << (b + 3))) a3 |= w[b + 3];
    }
    return (a0 | a1) | (a2 | a3);
}

__device__ __forceinline__ void diag_resolve(const unsigned (&D)[32], unsigned removed,
                                             unsigned& kept_out) {
    unsigned internal = removed, kept = 0u;
    #pragma unroll
    for (int b = 0; b < 32; b++) {
        if (!((internal >> b) & 1u)) { kept |= (1u << b); internal |= D[b]; }
    }
    kept_out = kept;
}

__global__ void __launch_bounds__(256, 1) scan_out_kernel(float* __restrict__ out) {
    const int t = threadIdx.x;
    __shared__ int s_ws[8];
    __shared__ unsigned s_keep[2];
    __shared__ int s_tot[2];
    __shared__ int s_sidx[NOUT];
    __shared__ int s_C;

    bool act = (t < WORDS);
    unsigned D[32], Abuf[32], Bbuf[32];
    unsigned removed = 0;
    int stop = TILES - 1;

    if (act) load_tile(D, t, t);
    if (act && t >= 1) load_tile(Abuf, t, 0);

    #pragma unroll 1
    for (int T = 0; T < TILES; T += 2) {
        if (act && t >= T + 2 && T + 1 < TILES) load_tile(Bbuf, t, T + 1);
        if (t == T) {
            unsigned kept;
            diag_resolve(D, removed, kept);
            s_keep[0] = kept;
            unsigned cv = (T == TILES - 1) ? (kept & 0xFFFFu) : kept;
            s_tot[0] = ((T == 0) ? 0 : s_tot[1]) + __popc(cv);
        }
        __syncthreads();
        {
            unsigned km = s_keep[0];
            if (act && t >= T) {
                if (t == T) removed |= or_sel(D, km);
                else        removed |= or_sel(Abuf, km);
            }
            if (s_tot[0] >= NOUT) { stop = T; break; }
        }
        if (T + 1 < TILES) {
            if (act && t >= T + 3 && T + 2 < TILES) load_tile(Abuf, t, T + 2);
            if (t == T + 1) {
                unsigned kept;
                diag_resolve(D, removed, kept);
                s_keep[1] = kept;
                unsigned cv = (T + 1 == TILES - 1) ? (kept & 0xFFFFu) : kept;
                s_tot[1] = s_tot[0] + __popc(cv);
            }
            __syncthreads();
            unsigned km = s_keep[1];
            if (act && t >= T + 1) {
                if (t == T + 1) removed |= or_sel(D, km);
                else            removed |= or_sel(Bbuf, km);
            }
            if (s_tot[1] >= NOUT) { stop = T + 1; break; }
        }
    }
    __syncthreads();

    // ---- select first 300 + output ----
    int L = min(KTOP, 32 * (stop + 1));
    int nb = L - 32 * t;
    nb = nb < 0 ? 0 : (nb > 32 ? 32 : nb);
    unsigned vmask = (nb >= 32) ? 0xFFFFFFFFu : ((nb > 0) ? ((1u << nb) - 1u) : 0u);

    unsigned rem = act ? removed : 0u;
    unsigned kept = (~rem) & vmask;
    int cnt = __popc(kept);
    int incl = bscan256(cnt, t, s_ws);
    int excl = incl - cnt;
    if (t == 255) s_C = incl;
    __syncthreads();
    int C = s_C;

    if (excl < NOUT && kept) {
        int r = excl;
        #pragma unroll 4
        for (int b = 0; b < 32; b++) {
            if ((kept >> b) & 1u) {
                if (r < NOUT) s_sidx[r] = t * 32 + b;
                r++;
            }
        }
    }
    __syncthreads();

    if (C < NOUT) {   // fill with suppressed (index ascending)
        unsigned sup = rem & vmask;
        int cnt2 = __popc(sup);
        int incl2 = bscan256(cnt2, t, s_ws);
        int b0 = C + (incl2 - cnt2);
        if (b0 < NOUT && sup) {
            #pragma unroll 4
            for (int b = 0; b < 32; b++) {
                if ((sup >> b) & 1u) {
                    if (b0 < NOUT) s_sidx[b0] = t * 32 + b;
                    b0++;
                }
            }
        }
        __syncthreads();
    }

    for (int r = t; r < NOUT; r += 256) {
        int idx = s_sidx[r];
        float4 f = g_tbox[idx];
        out[5 * r + 0] = 0.f;
        out[5 * r + 1] = f.x;
        out[5 * r + 2] = f.y;
        out[5 * r + 3] = f.z;
        out[5 * r + 4] = f.w;
    }
}

// ------------------------------ launch ---------------------------------------
extern "C" void kernel_launch(void* const* d_in, const int* in_sizes, int n_in,
                              void* d_out, int out_size) {
    const float* cls  = (const float*)d_in[0];   // (1,64,64,18)
    const float* bbox = (const float*)d_in[1];   // (1,64,64,36)
    float* out = (float*)d_out;                  // (300,5)

    proposal_kernel<<<NPROP / 256, 256>>>(cls, bbox);
    thresh_kernel<<<1, 256>>>();
    compact_kernel<<<NPROP / 256, 256>>>();
    rankscatter_kernel<<<NPROP / 256, 256>>>();
    dim3 mg(WORDS, KPAD / 128);
    mask_kernel<<<mg, 128>>>();
    scan_out_kernel<<<1, 256>>>(out);
}